// round 5
// baseline (speedup 1.0000x reference)
#include <cuda_runtime.h>

#define DD 8
#define BX 32            // m-pairs per block (tx) -> 64 m columns
#define BY 8             // ty; each thread does rows ty and ty+8 -> 16 n rows

typedef unsigned long long u64;

// packed f32x2 ops (Blackwell sm_103a)
#define FMA2(d,a,b,c) asm("fma.rn.f32x2 %0, %1, %2, %3;" : "=l"(d) : "l"(a), "l"(b), "l"(c))
#define MUL2(d,a,b)   asm("mul.rn.f32x2 %0, %1, %2;"     : "=l"(d) : "l"(a), "l"(b))
#define ADD2(d,a,b)   asm("add.rn.f32x2 %0, %1, %2;"     : "=l"(d) : "l"(a), "l"(b))

__device__ __forceinline__ u64 pack2(float lo, float hi) {
    u64 r; asm("mov.b64 %0, {%1, %2};" : "=l"(r) : "f"(lo), "f"(hi)); return r;
}
__device__ __forceinline__ void unpack2(u64 v, float& lo, float& hi) {
    asm("mov.b64 {%0, %1}, %2;" : "=f"(lo), "=f"(hi) : "l"(v));
}
__device__ __forceinline__ float ex2a(float x) {
    float r; asm("ex2.approx.f32 %0, %1;" : "=f"(r) : "f"(x)); return r;
}
__device__ __forceinline__ u64 dup(float v) {
    unsigned u = __float_as_uint(v);
    return ((u64)u << 32) | (u64)u;
}

// out[n,m] = sigma0 * E0 * ( S + corr )
//   d_k = (x1[n,k]-x2[m,k])^2 ; E_a = exp2( sum_k d_k * w[a,k] ), w = -0.5*log2e/L^2
//   S   = sum_j [ sum_c (KMm[c,j] E_c - Km[c,j] d_c E_c) ] * E_j * (lj2_j - d_j)
//   corr= sum_l ( F_l*poly_l - Kd_l*(Md_l-d_l)*(lj2_l-d_l) ) * E_l^2
//   poly_l = d_l*(c2_l*d_l - c1_l) + c3_l

__global__ __launch_bounds__(256, 1) void taylor_rbf_kernel(
    const float* __restrict__ x1, const float* __restrict__ x2,
    const float* __restrict__ L, const float* __restrict__ sig,
    float* __restrict__ out, int N, int M)
{
    __shared__ __align__(16) u64 wD[DD * DD];    // dup(w[a][k])
    __shared__ __align__(16) u64 ksD[DD * 16];   // per j: 8x dup(KMm[c][j]), 8x dup(-Km[c][j])
    __shared__ __align__(16) u64 plD[DD * 8];    // per j: (-c1,c2,c3,F,-Kd,Md,lj2,0)
    __shared__ __align__(16) u64 x1d[16 * DD];   // dup(x1[n0+r][k]), r=0..15
    __shared__ __align__(16) u64 nx2[DD * BX];   // (-x2[m0+2p][k], -x2[m0+2p+1][k])
    __shared__ u64 sig0d;

    const int tx = threadIdx.x;          // 0..31
    const int ty = threadIdx.y;          // 0..7
    const int tid = ty * BX + tx;

    // ---- per-block constant derivation ----
    if (tid < 64) {
        int c = tid >> 3, j = tid & 7;
        float Ljc = L[j * DD + c];
        float inv2_jc = 1.0f / (Ljc * Ljc);
        float L0c = L[c];
        float inv2_0c = 1.0f / (L0c * L0c);
        float Mcj = inv2_0c + inv2_jc;
        float L0j = L[j];
        float lj2 = L0j * L0j;
        float Kcj = sig[j] / (lj2 * lj2) * Mcj * Mcj;
        ksD[j * 16 + c]     = dup(Kcj / Mcj);
        ksD[j * 16 + 8 + c] = dup(-Kcj);
        float Lak = L[c * DD + j];
        wD[c * DD + j] = dup(-0.5f * 1.44269504088896340736f / (Lak * Lak));
        if (c == j) {
            int l = c;
            float tl = Mcj;
            plD[l * 8 + 0] = dup(-(5.0f * tl + lj2 * tl * tl));  // -c1
            plD[l * 8 + 1] = dup(tl * tl);                       //  c2
            plD[l * 8 + 2] = dup(2.0f + lj2 * tl);               //  c3
            plD[l * 8 + 3] = dup(sig[l] / (lj2 * lj2));          //  F
            plD[l * 8 + 4] = dup(-Kcj);                          // -Kd
            plD[l * 8 + 5] = dup(1.0f / Mcj);                    //  Md
            plD[l * 8 + 6] = dup(lj2);                           //  lj2
            plD[l * 8 + 7] = dup(0.0f);
        }
        if (tid == 0) sig0d = dup(sig[0]);
    }

    // ---- stage tiles ----
    const int n0 = blockIdx.y * 16, m0 = blockIdx.x * (2 * BX);
    {   // nx2: 256 entries, one per thread
        int k = tid >> 5, p = tid & 31;
        int mm = m0 + 2 * p;
        float a = (mm     < M) ? x2[mm * DD + k]       : 0.0f;
        float b = (mm + 1 < M) ? x2[(mm + 1) * DD + k] : 0.0f;
        nx2[k * BX + p] = pack2(-a, -b);
    }
    if (tid < 128) {  // x1d: 128 entries
        int r = tid >> 3, k = tid & 7;
        int nn = n0 + r;
        x1d[r * DD + k] = dup((nn < N) ? x1[nn * DD + k] : 0.0f);
    }
    __syncthreads();

    const int n = n0 + ty;           // pair A row
    const int n2 = n + 8;            // pair B row
    const int m = m0 + 2 * tx;
    if (m >= M) return;

    const u64 negone = dup(-1.0f);

    // ---- d for both rows ----
    u64 dA[DD], dB[DD];
#pragma unroll
    for (int k = 0; k < DD; k++) {
        u64 xv = nx2[k * BX + tx];
        u64 fa; ADD2(fa, x1d[ty * DD + k], xv);        MUL2(dA[k], fa, fa);
        u64 fb; ADD2(fb, x1d[(ty + 8) * DD + k], xv);  MUL2(dB[k], fb, fb);
    }

    // ---- E for both rows ----
    u64 EA[DD], EB[DD];
#pragma unroll
    for (int a = 0; a < DD; a++) {
        const ulonglong2* wr = reinterpret_cast<const ulonglong2*>(&wD[a * DD]);
        ulonglong2 p0 = wr[0], p1 = wr[1], p2 = wr[2], p3 = wr[3];
        u64 sA, sB;
        MUL2(sA, dA[0], p0.x);            MUL2(sB, dB[0], p0.x);
        FMA2(sA, dA[1], p0.y, sA);        FMA2(sB, dB[1], p0.y, sB);
        FMA2(sA, dA[2], p1.x, sA);        FMA2(sB, dB[2], p1.x, sB);
        FMA2(sA, dA[3], p1.y, sA);        FMA2(sB, dB[3], p1.y, sB);
        FMA2(sA, dA[4], p2.x, sA);        FMA2(sB, dB[4], p2.x, sB);
        FMA2(sA, dA[5], p2.y, sA);        FMA2(sB, dB[5], p2.y, sB);
        FMA2(sA, dA[6], p3.x, sA);        FMA2(sB, dB[6], p3.x, sB);
        FMA2(sA, dA[7], p3.y, sA);        FMA2(sB, dB[7], p3.y, sB);
        float lo, hi;
        unpack2(sA, lo, hi);  EA[a] = pack2(ex2a(lo), ex2a(hi));
        unpack2(sB, lo, hi);  EB[a] = pack2(ex2a(lo), ex2a(hi));
    }

    // ---- Q = d * E ----
    u64 QA[DD], QB[DD];
#pragma unroll
    for (int c = 0; c < DD; c++) { MUL2(QA[c], dA[c], EA[c]); MUL2(QB[c], dB[c], EB[c]); }

    // ---- merged S + corr loop over j ----
    u64 SA = dup(0.0f), SB = dup(0.0f);
#pragma unroll
    for (int j = 0; j < DD; j++) {
        const ulonglong2* kr = reinterpret_cast<const ulonglong2*>(&ksD[j * 16]);
        ulonglong2 a0 = kr[0], a1 = kr[1], a2 = kr[2], a3 = kr[3]; // KMm
        ulonglong2 b0 = kr[4], b1 = kr[5], b2 = kr[6], b3 = kr[7]; // -Km
        const ulonglong2* pr = reinterpret_cast<const ulonglong2*>(&plD[j * 8]);
        ulonglong2 q0 = pr[0], q1 = pr[1], q2 = pr[2], q3 = pr[3];

        u64 accA, accB;
        MUL2(accA, a0.x, EA[0]);          MUL2(accB, a0.x, EB[0]);
        FMA2(accA, a0.y, EA[1], accA);    FMA2(accB, a0.y, EB[1], accB);
        FMA2(accA, a1.x, EA[2], accA);    FMA2(accB, a1.x, EB[2], accB);
        FMA2(accA, a1.y, EA[3], accA);    FMA2(accB, a1.y, EB[3], accB);
        FMA2(accA, a2.x, EA[4], accA);    FMA2(accB, a2.x, EB[4], accB);
        FMA2(accA, a2.y, EA[5], accA);    FMA2(accB, a2.y, EB[5], accB);
        FMA2(accA, a3.x, EA[6], accA);    FMA2(accB, a3.x, EB[6], accB);
        FMA2(accA, a3.y, EA[7], accA);    FMA2(accB, a3.y, EB[7], accB);
        FMA2(accA, b0.x, QA[0], accA);    FMA2(accB, b0.x, QB[0], accB);
        FMA2(accA, b0.y, QA[1], accA);    FMA2(accB, b0.y, QB[1], accB);
        FMA2(accA, b1.x, QA[2], accA);    FMA2(accB, b1.x, QB[2], accB);
        FMA2(accA, b1.y, QA[3], accA);    FMA2(accB, b1.y, QB[3], accB);
        FMA2(accA, b2.x, QA[4], accA);    FMA2(accB, b2.x, QB[4], accB);
        FMA2(accA, b2.y, QA[5], accA);    FMA2(accB, b2.y, QB[5], accB);
        FMA2(accA, b3.x, QA[6], accA);    FMA2(accB, b3.x, QB[6], accB);
        FMA2(accA, b3.y, QA[7], accA);    FMA2(accB, b3.y, QB[7], accB);

        // pair A: S term + diag correction (shares t = lj2 - d)
        {
            u64 t;  FMA2(t, dA[j], negone, q3.x);        // lj2 - d
            u64 et; MUL2(et, EA[j], t);
            FMA2(SA, accA, et, SA);
            u64 E2; MUL2(E2, EA[j], EA[j]);
            u64 u;  FMA2(u, dA[j], q0.y, q0.x);          // c2*d - c1
            u64 py; FMA2(py, dA[j], u, q1.x);            // poly
            u64 dd; MUL2(dd, py, q1.y);                  // F*poly
            u64 t1; FMA2(t1, dA[j], negone, q2.y);       // Md - d
            u64 t3; MUL2(t3, t1, t);
            FMA2(dd, t3, q2.x, dd);                      // - Kd*t3
            FMA2(SA, dd, E2, SA);
        }
        // pair B
        {
            u64 t;  FMA2(t, dB[j], negone, q3.x);
            u64 et; MUL2(et, EB[j], t);
            FMA2(SB, accB, et, SB);
            u64 E2; MUL2(E2, EB[j], EB[j]);
            u64 u;  FMA2(u, dB[j], q0.y, q0.x);
            u64 py; FMA2(py, dB[j], u, q1.x);
            u64 dd; MUL2(dd, py, q1.y);
            u64 t1; FMA2(t1, dB[j], negone, q2.y);
            u64 t3; MUL2(t3, t1, t);
            FMA2(dd, t3, q2.x, dd);
            FMA2(SB, dd, E2, SB);
        }
    }

    // ---- out = sig0 * E0 * (S + corr) ----
    u64 s0 = sig0d;
    u64 eA; MUL2(eA, EA[0], s0);
    u64 eB; MUL2(eB, EB[0], s0);
    u64 rA; MUL2(rA, SA, eA);
    u64 rB; MUL2(rB, SB, eB);

    bool full = (m + 1 < M);
    if (n < N) {
        long idx = (long)n * M + m;
        if (full) *reinterpret_cast<u64*>(&out[idx]) = rA;
        else { float lo, hi; unpack2(rA, lo, hi); out[idx] = lo; }
    }
    if (n2 < N) {
        long idx = (long)n2 * M + m;
        if (full) *reinterpret_cast<u64*>(&out[idx]) = rB;
        else { float lo, hi; unpack2(rB, lo, hi); out[idx] = lo; }
    }
}

extern "C" void kernel_launch(void* const* d_in, const int* in_sizes, int n_in,
                              void* d_out, int out_size)
{
    const float* x1  = (const float*)d_in[0];
    const float* x2  = (const float*)d_in[1];
    const float* L   = (const float*)d_in[2];
    const float* sig = (const float*)d_in[3];
    float* out = (float*)d_out;

    int N = in_sizes[0] / DD;
    int M = in_sizes[1] / DD;

    dim3 block(BX, BY);                                    // 256 threads
    dim3 grid((M + 2 * BX - 1) / (2 * BX), (N + 15) / 16);
    taylor_rbf_kernel<<<grid, block>>>(x1, x2, L, sig, out, N, M);
}

// round 6
// speedup vs baseline: 1.3970x; 1.3970x over previous
#include <cuda_runtime.h>

#define DD 8
#define BX 32            // m-pairs per block (tx) -> 64 m columns
#define BY 8             // ty; each thread does rows ty and ty+8 -> 16 n rows

typedef unsigned long long u64;

// packed f32x2 ops (Blackwell sm_103a)
#define FMA2(d,a,b,c) asm("fma.rn.f32x2 %0, %1, %2, %3;" : "=l"(d) : "l"(a), "l"(b), "l"(c))
#define MUL2(d,a,b)   asm("mul.rn.f32x2 %0, %1, %2;"     : "=l"(d) : "l"(a), "l"(b))
#define ADD2(d,a,b)   asm("add.rn.f32x2 %0, %1, %2;"     : "=l"(d) : "l"(a), "l"(b))

__device__ __forceinline__ u64 pack2(float lo, float hi) {
    u64 r; asm("mov.b64 %0, {%1, %2};" : "=l"(r) : "f"(lo), "f"(hi)); return r;
}
__device__ __forceinline__ void unpack2(u64 v, float& lo, float& hi) {
    asm("mov.b64 {%0, %1}, %2;" : "=f"(lo), "=f"(hi) : "l"(v));
}
__device__ __forceinline__ float ex2a(float x) {
    float r; asm("ex2.approx.f32 %0, %1;" : "=f"(r) : "f"(x)); return r;
}
__device__ __forceinline__ u64 dup(float v) {
    unsigned u = __float_as_uint(v);
    return ((u64)u << 32) | (u64)u;
}

// out[n,m] = sigma0 * E0 * S_total
//   d_k = (x1[n,k]-x2[m,k])^2 ; E_a = exp2( sum_k d_k * w[a,k] ), w = -0.5*log2e/L^2
//   S_total = sum_j [ sum_c (KMm[c,j] - Km[c,j] d_c) E_c ] * E_j * (lj2_j - d_j)
//           + sum_j (alpha_j + beta_j d_j + gamma_j d_j^2) * E_j^2
// with alpha = F*c3 - Kd*Md*lj2, beta = -F*c1 + Kd*(Md+lj2), gamma = F*c2 - Kd

__global__ __launch_bounds__(256, 2) void taylor_rbf_kernel(
    const float* __restrict__ x1, const float* __restrict__ x2,
    const float* __restrict__ L, const float* __restrict__ sig,
    float* __restrict__ out, int N, int M)
{
    __shared__ __align__(16) u64 wD[DD * DD];    // dup(w[a][k])
    __shared__ __align__(16) u64 ksD[DD * 16];   // per j: 8x dup(KMm[c][j]), 8x dup(-Km[c][j])
    __shared__ __align__(16) u64 plD[DD * 4];    // per j: (lj2, alpha, beta, gamma)
    __shared__ __align__(16) u64 x1d[16 * DD];   // dup(x1[n0+r][k]), r=0..15
    __shared__ __align__(16) u64 nx2[DD * BX];   // (-x2[m0+2p][k], -x2[m0+2p+1][k])
    __shared__ u64 sig0d;

    const int tx = threadIdx.x;          // 0..31
    const int ty = threadIdx.y;          // 0..7
    const int tid = ty * BX + tx;

    // ---- per-block constant derivation ----
    if (tid < 64) {
        int c = tid >> 3, j = tid & 7;
        float Ljc = L[j * DD + c];
        float inv2_jc = 1.0f / (Ljc * Ljc);
        float L0c = L[c];
        float inv2_0c = 1.0f / (L0c * L0c);
        float Mcj = inv2_0c + inv2_jc;
        float L0j = L[j];
        float lj2 = L0j * L0j;
        float Kcj = sig[j] / (lj2 * lj2) * Mcj * Mcj;
        ksD[j * 16 + c]     = dup(Kcj / Mcj);
        ksD[j * 16 + 8 + c] = dup(-Kcj);
        float Lak = L[c * DD + j];
        wD[c * DD + j] = dup(-0.5f * 1.44269504088896340736f / (Lak * Lak));
        if (c == j) {
            int l = c;
            float tl = Mcj;                       // M[l][l]
            float c1 = 5.0f * tl + lj2 * tl * tl;
            float c2 = tl * tl;
            float c3 = 2.0f + lj2 * tl;
            float F  = sig[l] / (lj2 * lj2);
            float Kd = Kcj;
            float Md = 1.0f / tl;
            plD[l * 4 + 0] = dup(lj2);
            plD[l * 4 + 1] = dup(F * c3 - Kd * Md * lj2);      // alpha
            plD[l * 4 + 2] = dup(-F * c1 + Kd * (Md + lj2));   // beta
            plD[l * 4 + 3] = dup(F * c2 - Kd);                 // gamma
        }
        if (tid == 0) sig0d = dup(sig[0]);
    }

    // ---- stage tiles ----
    const int n0 = blockIdx.y * 16, m0 = blockIdx.x * (2 * BX);
    {   // nx2: 256 entries, one per thread
        int k = tid >> 5, p = tid & 31;
        int mm = m0 + 2 * p;
        float a = (mm     < M) ? x2[mm * DD + k]       : 0.0f;
        float b = (mm + 1 < M) ? x2[(mm + 1) * DD + k] : 0.0f;
        nx2[k * BX + p] = pack2(-a, -b);
    }
    if (tid < 128) {  // x1d: 128 entries
        int r = tid >> 3, k = tid & 7;
        int nn = n0 + r;
        x1d[r * DD + k] = dup((nn < N) ? x1[nn * DD + k] : 0.0f);
    }
    __syncthreads();

    const int n = n0 + ty;           // pair A row
    const int n2 = n + 8;            // pair B row
    const int m = m0 + 2 * tx;
    if (m >= M) return;

    const u64 negone = dup(-1.0f);

    // ---- d for both rows ----
    u64 dA[DD], dB[DD];
#pragma unroll
    for (int k = 0; k < DD; k++) {
        u64 xv = nx2[k * BX + tx];
        u64 fa; ADD2(fa, x1d[ty * DD + k], xv);        MUL2(dA[k], fa, fa);
        u64 fb; ADD2(fb, x1d[(ty + 8) * DD + k], xv);  MUL2(dB[k], fb, fb);
    }

    // ---- E for both rows ----
    u64 EA[DD], EB[DD];
#pragma unroll
    for (int a = 0; a < DD; a++) {
        const ulonglong2* wr = reinterpret_cast<const ulonglong2*>(&wD[a * DD]);
        ulonglong2 p0 = wr[0], p1 = wr[1], p2 = wr[2], p3 = wr[3];
        u64 sA, sB;
        MUL2(sA, dA[0], p0.x);            MUL2(sB, dB[0], p0.x);
        FMA2(sA, dA[1], p0.y, sA);        FMA2(sB, dB[1], p0.y, sB);
        FMA2(sA, dA[2], p1.x, sA);        FMA2(sB, dB[2], p1.x, sB);
        FMA2(sA, dA[3], p1.y, sA);        FMA2(sB, dB[3], p1.y, sB);
        FMA2(sA, dA[4], p2.x, sA);        FMA2(sB, dB[4], p2.x, sB);
        FMA2(sA, dA[5], p2.y, sA);        FMA2(sB, dB[5], p2.y, sB);
        FMA2(sA, dA[6], p3.x, sA);        FMA2(sB, dB[6], p3.x, sB);
        FMA2(sA, dA[7], p3.y, sA);        FMA2(sB, dB[7], p3.y, sB);
        float lo, hi;
        unpack2(sA, lo, hi);  EA[a] = pack2(ex2a(lo), ex2a(hi));
        unpack2(sB, lo, hi);  EB[a] = pack2(ex2a(lo), ex2a(hi));
    }

    // ---- merged S + corr loop over j ----
    u64 SA = dup(0.0f), SB = dup(0.0f);
#pragma unroll
    for (int j = 0; j < DD; j++) {
        const ulonglong2* kr = reinterpret_cast<const ulonglong2*>(&ksD[j * 16]);
        ulonglong2 a0 = kr[0], a1 = kr[1], a2 = kr[2], a3 = kr[3]; // KMm
        ulonglong2 b0 = kr[4], b1 = kr[5], b2 = kr[6], b3 = kr[7]; // -Km
        const ulonglong2* pr = reinterpret_cast<const ulonglong2*>(&plD[j * 4]);
        ulonglong2 q0 = pr[0];   // (lj2, alpha)
        ulonglong2 q1 = pr[1];   // (beta, gamma)

        u64 accA, accB, wp;
        // pair A matvec: acc += (KMm_c - Km_c * d_c) * E_c
        FMA2(wp, b0.x, dA[0], a0.x);  MUL2(accA, wp, EA[0]);
        FMA2(wp, b0.y, dA[1], a0.y);  FMA2(accA, wp, EA[1], accA);
        FMA2(wp, b1.x, dA[2], a1.x);  FMA2(accA, wp, EA[2], accA);
        FMA2(wp, b1.y, dA[3], a1.y);  FMA2(accA, wp, EA[3], accA);
        FMA2(wp, b2.x, dA[4], a2.x);  FMA2(accA, wp, EA[4], accA);
        FMA2(wp, b2.y, dA[5], a2.y);  FMA2(accA, wp, EA[5], accA);
        FMA2(wp, b3.x, dA[6], a3.x);  FMA2(accA, wp, EA[6], accA);
        FMA2(wp, b3.y, dA[7], a3.y);  FMA2(accA, wp, EA[7], accA);
        // pair B matvec
        FMA2(wp, b0.x, dB[0], a0.x);  MUL2(accB, wp, EB[0]);
        FMA2(wp, b0.y, dB[1], a0.y);  FMA2(accB, wp, EB[1], accB);
        FMA2(wp, b1.x, dB[2], a1.x);  FMA2(accB, wp, EB[2], accB);
        FMA2(wp, b1.y, dB[3], a1.y);  FMA2(accB, wp, EB[3], accB);
        FMA2(wp, b2.x, dB[4], a2.x);  FMA2(accB, wp, EB[4], accB);
        FMA2(wp, b2.y, dB[5], a2.y);  FMA2(accB, wp, EB[5], accB);
        FMA2(wp, b3.x, dB[6], a3.x);  FMA2(accB, wp, EB[6], accB);
        FMA2(wp, b3.y, dB[7], a3.y);  FMA2(accB, wp, EB[7], accB);

        // pair A tail: S += acc*E_j*(lj2-d_j) + (alpha + beta d + gamma d^2)*E_j^2
        {
            u64 t;  FMA2(t, dA[j], negone, q0.x);        // lj2 - d
            u64 et; MUL2(et, EA[j], t);
            FMA2(SA, accA, et, SA);
            u64 E2; MUL2(E2, EA[j], EA[j]);
            u64 u;  FMA2(u, q1.y, dA[j], q1.x);          // gamma*d + beta
            u64 py; FMA2(py, dA[j], u, q0.y);            // d*(.) + alpha
            FMA2(SA, py, E2, SA);
        }
        // pair B tail
        {
            u64 t;  FMA2(t, dB[j], negone, q0.x);
            u64 et; MUL2(et, EB[j], t);
            FMA2(SB, accB, et, SB);
            u64 E2; MUL2(E2, EB[j], EB[j]);
            u64 u;  FMA2(u, q1.y, dB[j], q1.x);
            u64 py; FMA2(py, dB[j], u, q0.y);
            FMA2(SB, py, E2, SB);
        }
    }

    // ---- out = sig0 * E0 * S ----
    u64 s0 = sig0d;
    u64 eA; MUL2(eA, EA[0], s0);
    u64 eB; MUL2(eB, EB[0], s0);
    u64 rA; MUL2(rA, SA, eA);
    u64 rB; MUL2(rB, SB, eB);

    bool full = (m + 1 < M);
    if (n < N) {
        long idx = (long)n * M + m;
        if (full) *reinterpret_cast<u64*>(&out[idx]) = rA;
        else { float lo, hi; unpack2(rA, lo, hi); out[idx] = lo; }
    }
    if (n2 < N) {
        long idx = (long)n2 * M + m;
        if (full) *reinterpret_cast<u64*>(&out[idx]) = rB;
        else { float lo, hi; unpack2(rB, lo, hi); out[idx] = lo; }
    }
}

extern "C" void kernel_launch(void* const* d_in, const int* in_sizes, int n_in,
                              void* d_out, int out_size)
{
    const float* x1  = (const float*)d_in[0];
    const float* x2  = (const float*)d_in[1];
    const float* L   = (const float*)d_in[2];
    const float* sig = (const float*)d_in[3];
    float* out = (float*)d_out;

    int N = in_sizes[0] / DD;
    int M = in_sizes[1] / DD;

    dim3 block(BX, BY);                                    // 256 threads
    dim3 grid((M + 2 * BX - 1) / (2 * BX), (N + 15) / 16);
    taylor_rbf_kernel<<<grid, block>>>(x1, x2, L, sig, out, N, M);
}